// round 9
// baseline (speedup 1.0000x reference)
#include <cuda_runtime.h>
#include <math_constants.h>

// ZBL repulsion, R7: two-pipe gather (216KB smem slice + L2 LDG), with
// branch-free predicated fetches and a split fetch/compute loop body so all
// 8 atom gathers per iteration issue back-to-back (high MLP_p1). rsqrt gives
// dr and 1/dr from one MUFU op.

static constexpr int MAX_ATOMS  = 131072;
static constexpr int SMEM_ATOMS = 27648;               // 27648 * 8B = 216KB
static constexpr float R_MAX  = 6.0f;
static constexpr float QSCALE = 512.0f;
static constexpr float R2_MIN_U = (0.02f * QSCALE) * (0.02f * QSCALE); // 104.8576
static constexpr float RMAX_U   = R_MAX * QSCALE;      // 3072

__device__ int2   g_atoms[MAX_ATOMS];
__device__ float  g_powtab[64];
__device__ double g_acc;
__device__ unsigned int g_done;

// ---------------------------------------------------------------------------
__global__ void prep_kernel(const float* __restrict__ R,
                            const int* __restrict__ Z, int n,
                            const float* __restrict__ a_exp) {
    if (blockIdx.x == 0) {
        if (threadIdx.x < 64) g_powtab[threadIdx.x] = powf((float)threadIdx.x, a_exp[0]);
        if (threadIdx.x == 0) { g_acc = 0.0; g_done = 0u; }
    }
    int i = blockIdx.x * blockDim.x + threadIdx.x;
    if (i < n) {
        int xq = __float2int_rn(R[3 * i + 0] * QSCALE);
        int yq = __float2int_rn(R[3 * i + 1] * QSCALE);
        int zq = __float2int_rn(R[3 * i + 2] * QSCALE);
        int z  = Z[i];
        g_atoms[i] = make_int2((xq & 0xFFFF) | (yq << 16),
                               (zq & 0xFFFF) | (z << 16));
    }
}

// ---------------------------------------------------------------------------
// Branch-free: LDS always issues (clamped slot), LDG predicated-overrides.
// Single-statement if -> @P LDG.64, no BSSY/BSYNC, loads batch freely.
__device__ __forceinline__ int2 fetch_atom(int k, const int2* __restrict__ s_atoms) {
    int ks = (k < SMEM_ATOMS) ? k : 0;
    int2 v = s_atoms[ks];
    if (k >= SMEM_ATOMS) v = __ldg(&g_atoms[k]);
    return v;
}

__device__ __forceinline__ float edge_compute(int2 vi, int2 vj, bool valid,
                                              float inv_anum,
                                              float c0, float c1, float c2, float c3,
                                              float e0, float e1, float e2, float e3,
                                              const float* __restrict__ s_pow) {
    // sign-extended 16-bit coordinate deltas (exact integer arithmetic)
    int dxq = ((vj.x << 16) >> 16) - ((vi.x << 16) >> 16);
    int dyq = (vj.x >> 16)         - (vi.x >> 16);
    int dzq = ((vj.y << 16) >> 16) - ((vi.y << 16) >> 16);

    float dx = (float)dxq;
    float dy = (float)dyq;
    float dz = (float)dzq;
    float r2 = fmaf(dx, dx, fmaf(dy, dy, dz * dz));   // units^2
    r2 = fmaxf(r2, R2_MIN_U);                         // == clip(dr, 0.02, ...)
    float inv_ru = rsqrtf(r2);                        // one MUFU: dr AND 1/dr
    float dru = r2 * inv_ru;                          // dr in units

    float res = 0.0f;
    if (valid & (dru < RMAX_U)) {   // cosine cutoff exactly 0 at dr >= R_MAX
        float dr     = dru * (1.0f / QSCALE);
        float inv_dr = inv_ru * QSCALE;
        int Zi = vi.y >> 16;
        int Zj = vj.y >> 16;
        float cut = 0.5f * (__cosf(dr * (CUDART_PI_F / R_MAX)) + 1.0f);
        float zp  = s_pow[Zi] + s_pow[Zj];
        float dist = dr * zp * inv_anum;
        float f = c0 * __expf(-e0 * dist);
        f = fmaf(c1, __expf(-e1 * dist), f);
        f = fmaf(c2, __expf(-e2 * dist), f);
        f = fmaf(c3, __expf(-e3 * dist), f);
        res = 0.5f * (float)Zi * (float)Zj * f * cut * inv_dr;
    }
    return res;
}

extern __shared__ int2 s_atoms[];   // SMEM_ATOMS records (216KB dynamic)

__global__ void __launch_bounds__(1024, 1)
edge_kernel(const int* __restrict__ idx, int E, int n_atoms,
            const float* __restrict__ a_num,
            const float* __restrict__ coef,
            const float* __restrict__ expo,
            float* __restrict__ out) {
    __shared__ float s_pow[64];
    __shared__ float s_red[32];

    int t = threadIdx.x;
    if (t < 64) s_pow[t] = g_powtab[t];
    int slice = (n_atoms < SMEM_ATOMS) ? n_atoms : SMEM_ATOMS;
    for (int k = t; k < slice; k += blockDim.x) s_atoms[k] = g_atoms[k];
    __syncthreads();

    float inv_anum = __fdividef(1.0f, __ldg(a_num));
    float c0 = __ldg(coef + 0), c1 = __ldg(coef + 1);
    float c2 = __ldg(coef + 2), c3 = __ldg(coef + 3);
    float e0 = __ldg(expo + 0), e1 = __ldg(expo + 1);
    float e2 = __ldg(expo + 2), e3 = __ldg(expo + 3);

    int nvec = E >> 2;  // int4 chunks
    const int4* __restrict__ ii = (const int4*)idx;
    const int4* __restrict__ jj = (const int4*)(idx + E);

    float acc = 0.0f;
    int stride = gridDim.x * blockDim.x;
    for (int v = blockIdx.x * blockDim.x + t; v < nvec; v += stride) {
        int4 a = __ldg(ii + v);
        int4 b = __ldg(jj + v);

        int ki[4] = {a.x, a.y, a.z, a.w};
        int kj[4] = {b.x, b.y, b.z, b.w};
        bool val[4];
        int2 vi[4], vj[4];

        // fetch phase: 8 branch-free gathers, batched for MLP
        #pragma unroll
        for (int e = 0; e < 4; e++) {
            val[e] = ((unsigned)ki[e] < (unsigned)n_atoms) &
                     ((unsigned)kj[e] < (unsigned)n_atoms);
            int ia = val[e] ? ki[e] : 0;
            int ja = val[e] ? kj[e] : 0;
            vi[e] = fetch_atom(ia, s_atoms);
            vj[e] = fetch_atom(ja, s_atoms);
        }
        // compute phase
        #pragma unroll
        for (int e = 0; e < 4; e++) {
            acc += edge_compute(vi[e], vj[e], val[e], inv_anum,
                                c0, c1, c2, c3, e0, e1, e2, e3, s_pow);
        }
    }
    // tail edges (E not multiple of 4)
    if (blockIdx.x == 0 && t == 0) {
        for (int e = nvec << 2; e < E; e++) {
            int ia = idx[e], ja = idx[E + e];
            bool va = ((unsigned)ia < (unsigned)n_atoms) &
                      ((unsigned)ja < (unsigned)n_atoms);
            int2 vi2 = fetch_atom(va ? ia : 0, s_atoms);
            int2 vj2 = fetch_atom(va ? ja : 0, s_atoms);
            acc += edge_compute(vi2, vj2, va, inv_anum,
                                c0, c1, c2, c3, e0, e1, e2, e3, s_pow);
        }
    }

    // warp reduce
    #pragma unroll
    for (int o = 16; o > 0; o >>= 1)
        acc += __shfl_down_sync(0xFFFFFFFFu, acc, o);
    int lane = t & 31, wid = t >> 5;
    if (lane == 0) s_red[wid] = acc;
    __syncthreads();
    if (wid == 0) {
        float vsum = (t < (int)(blockDim.x >> 5)) ? s_red[t] : 0.0f;
        #pragma unroll
        for (int o = 16; o > 0; o >>= 1)
            vsum += __shfl_down_sync(0xFFFFFFFFu, vsum, o);
        if (t == 0) {
            atomicAdd(&g_acc, (double)vsum);
            __threadfence();
            unsigned int ticket = atomicAdd(&g_done, 1u);
            if (ticket == gridDim.x - 1) {
                double total = atomicAdd(&g_acc, 0.0);
                out[0] = (float)total;
            }
        }
    }
}

// ---------------------------------------------------------------------------
extern "C" void kernel_launch(void* const* d_in, const int* in_sizes, int n_in,
                              void* d_out, int out_size) {
    const float* R     = (const float*)d_in[0];
    const int*   Z     = (const int*)d_in[1];
    const int*   idx   = (const int*)d_in[2];
    const float* a_exp = (const float*)d_in[3];
    const float* a_num = (const float*)d_in[4];
    const float* coef  = (const float*)d_in[5];
    const float* expo  = (const float*)d_in[6];
    float* out = (float*)d_out;

    int n_atoms = in_sizes[1];
    int E = in_sizes[2] / 2;

    int pb = (n_atoms + 255) / 256;
    if (pb < 1) pb = 1;
    prep_kernel<<<pb, 256>>>(R, Z, n_atoms, a_exp);

    int smem_bytes = SMEM_ATOMS * (int)sizeof(int2);   // 221184
    cudaFuncSetAttribute(edge_kernel,
                         cudaFuncAttributeMaxDynamicSharedMemorySize, smem_bytes);

    int nsm = 148;
    cudaDeviceGetAttribute(&nsm, cudaDevAttrMultiProcessorCount, 0);
    int blocks = nsm;          // persistent: 1 CTA per SM
    if (blocks < 1) blocks = 1;

    edge_kernel<<<blocks, 1024, smem_bytes>>>(idx, E, n_atoms, a_num, coef, expo, out);
}